// round 3
// baseline (speedup 1.0000x reference)
#include <cuda_runtime.h>
#include <cuda_bf16.h>
#include <cstdint>

#define BB   128
#define SS   64
#define DD   32
#define ND   200000
#define NNZT 4000000
#define TN   256
#define SDS  258            // bf16 sd stride -> conflict-free column reads
#define NW   6250           // ND/32 words per drugs row
#define WPR  6256           // padded words-per-row

// ---------------- device scratch ----------------
__device__ float    g_s_set[BB * DD];
__device__ float    g_common[BB * DD];
__device__ float    g_row_a[ND];
__device__ float    g_colsum[ND];
__device__ float    g_diffacc[BB * DD];
__device__ float    g_sdiff[BB];
__device__ unsigned g_bits[BB * WPR];
__device__ double   g_bce;
__device__ double   g_neg1;

// ---------------- packed f32x2 helpers ----------------
__device__ __forceinline__ unsigned long long pk2(float lo, float hi) {
    unsigned long long r;
    asm("mov.b64 %0, {%1, %2};" : "=l"(r) : "f"(lo), "f"(hi));
    return r;
}
__device__ __forceinline__ void ffma2(unsigned long long& acc,
                                      unsigned long long a, unsigned long long b) {
    asm("fma.rn.f32x2 %0, %1, %2, %0;" : "+l"(acc) : "l"(a), "l"(b));
}
__device__ __forceinline__ float hsum2(unsigned long long a, unsigned long long b) {
    unsigned long long s;
    asm("add.rn.f32x2 %0, %1, %2;" : "=l"(s) : "l"(a), "l"(b));
    float x, y;
    asm("mov.b64 {%0, %1}, %2;" : "=f"(x), "=f"(y) : "l"(s));
    return x + y;
}

// ---------------- kernel 0: zero accumulators ----------------
__global__ void k_init() {
    int i = blockIdx.x * blockDim.x + threadIdx.x;
    int stride = gridDim.x * blockDim.x;
    for (int j = i; j < ND; j += stride) g_row_a[j] = 0.f;
    for (int j = i; j < BB * WPR; j += stride) g_bits[j] = 0u;
    if (i < BB * DD) g_diffacc[i] = 0.f;
    if (i < BB) g_sdiff[i] = 0.f;
    if (i == 0) { g_bce = 0.0; g_neg1 = 0.0; }
}

// ---------------- kernel 1: pack binary drugs matrix to bits --------------
__global__ void k_pack(const float* __restrict__ drugs) {
    int lane = threadIdx.x & 31;
    int gw = blockIdx.x * (blockDim.x >> 5) + (threadIdx.x >> 5);
    int wstride = gridDim.x * (blockDim.x >> 5);
    int total = BB * NW;
    for (; gw < total; gw += wstride) {
        int row = gw / NW, word = gw - row * NW;
        float v = drugs[(size_t)row * ND + word * 32 + lane];
        unsigned m = __ballot_sync(0xffffffffu, v != 0.f);
        if (lane == 0) g_bits[row * WPR + word] = m;
    }
}

// ---------------- kernel 2: s_set (normalized) + common_embed ----------------
__global__ void k_attn(const int* __restrict__ syms, const int* __restrict__ simidx,
                       const float* __restrict__ sym_emb,
                       const float* __restrict__ w, const float* __restrict__ bvec) {
    int b = blockIdx.x;
    int s = threadIdx.x;
    __shared__ float sw[DD];
    __shared__ float sl[SS];
    __shared__ float sred[SS][DD];
    __shared__ float smax, ssum;
    if (s < DD) sw[s] = w[s];
    float b0 = bvec[0];
    __syncthreads();

    // ---- phase A: s_set ----
    int sym = syms[b * SS + s];
    float x[DD];
    {
        const float4* rp = (const float4*)(sym_emb + (size_t)sym * DD);
#pragma unroll
        for (int q = 0; q < DD / 4; q++) {
            float4 v = rp[q];
            x[4 * q + 0] = v.x; x[4 * q + 1] = v.y; x[4 * q + 2] = v.z; x[4 * q + 3] = v.w;
        }
    }
    float lg = 0.f;
#pragma unroll
    for (int k = 0; k < DD; k++) lg += x[k] * sw[k];
    lg += b0;
    sl[s] = lg;
    __syncthreads();
    if (s == 0) { float m = sl[0]; for (int j = 1; j < SS; j++) m = fmaxf(m, sl[j]); smax = m; }
    __syncthreads();
    float e = expf(lg - smax);
    sl[s] = e;
    __syncthreads();
    if (s == 0) { float t = 0.f; for (int j = 0; j < SS; j++) t += sl[j]; ssum = t; }
    __syncthreads();
    float alpha = e / ssum;
#pragma unroll
    for (int k = 0; k < DD; k++) sred[s][k] = alpha * x[k];
    __syncthreads();
    if (s < DD) {
        float acc = 0.f;
        for (int j = 0; j < SS; j++) acc += sred[j][s];
        float sq = acc * acc;
#pragma unroll
        for (int off = 16; off; off >>= 1) sq += __shfl_xor_sync(0xffffffffu, sq, off);
        float nrm = fmaxf(sqrtf(sq), 1e-12f);
        g_s_set[b * DD + s] = acc / nrm;
    }
    __syncthreads();

    // ---- phase B: common_embed ----
    int sb = simidx[b];
    int sym2 = syms[sb * SS + s];
    float vals = (float)(sym * sym2);
    float y[DD];
    {
        const float4* rp = (const float4*)(sym_emb + (size_t)s * DD);
#pragma unroll
        for (int q = 0; q < DD / 4; q++) {
            float4 v = rp[q];
            y[4 * q + 0] = vals * v.x; y[4 * q + 1] = vals * v.y;
            y[4 * q + 2] = vals * v.z; y[4 * q + 3] = vals * v.w;
        }
    }
    lg = 0.f;
#pragma unroll
    for (int k = 0; k < DD; k++) lg += y[k] * sw[k];
    lg += b0;
    sl[s] = lg;
    __syncthreads();
    if (s == 0) { float m = sl[0]; for (int j = 1; j < SS; j++) m = fmaxf(m, sl[j]); smax = m; }
    __syncthreads();
    e = expf(lg - smax);
    sl[s] = e;
    __syncthreads();
    if (s == 0) { float t = 0.f; for (int j = 0; j < SS; j++) t += sl[j]; ssum = t; }
    __syncthreads();
    alpha = e / ssum;
#pragma unroll
    for (int k = 0; k < DD; k++) sred[s][k] = alpha * y[k];
    __syncthreads();
    if (s < DD) {
        float acc = 0.f;
        for (int j = 0; j < SS; j++) acc += sred[j][s];
        g_common[b * DD + s] = acc;
    }
}

// ---------------- kernel 3: fused mainloop (no global loads in hot loop) ----
__global__ void __launch_bounds__(256, 3) k_main(
    const int* __restrict__ simidx,
    const float* __restrict__ drug_emb, float* __restrict__ out) {
    extern __shared__ float smem[];
    __nv_bfloat16* sd16 = (__nv_bfloat16*)smem;            // [DD][SDS] bf16
    float*    s_s   = smem + (DD * SDS) / 2;               // [BB*DD]
    float*    s_c   = s_s + BB * DD;                       // [BB*DD]
    float*    s_acc = s_c + BB * DD;                       // [BB*DD]
    unsigned* s_bit = (unsigned*)(s_acc + BB * DD);        // [BB*8]
    float*    s_sd  = (float*)(s_bit + BB * 8);            // [BB]
    float*    s_red = s_sd + BB;                           // [256]
    int*      s_sim = (int*)(s_red + 256);                 // [BB]

    int tid = threadIdx.x;
    int n0 = blockIdx.x * TN;
    int n = n0 + tid;
    bool valid = (n < ND);

    for (int i = tid; i < BB * DD; i += 256) {
        s_s[i] = g_s_set[i];
        s_c[i] = g_common[i];
        s_acc[i] = 0.f;
    }
    if (tid < BB) { s_sim[tid] = simidx[tid]; s_sd[tid] = 0.f; }
    // load this block's 256-bit slice of every drugs row (8 words x 128 rows)
    int w0 = n0 >> 5;
    for (int i = tid; i < BB * 8; i += 256)
        s_bit[i] = g_bits[(i >> 3) * WPR + w0 + (i & 7)];

    // per-thread d row, normalized in regs
    float dreg[DD];
    {
        int gn = valid ? n : (ND - 1);
        const float4* rp = (const float4*)(drug_emb + (size_t)(gn + 1) * DD);
        float sqs = 0.f;
#pragma unroll
        for (int q = 0; q < DD / 4; q++) {
            float4 v = rp[q];
            dreg[4 * q + 0] = v.x; dreg[4 * q + 1] = v.y;
            dreg[4 * q + 2] = v.z; dreg[4 * q + 3] = v.w;
            sqs += v.x * v.x + v.y * v.y + v.z * v.z + v.w * v.w;
        }
        float inv = 1.0f / fmaxf(sqrtf(sqs), 1e-12f);
        if (!valid) inv = 0.f;
#pragma unroll
        for (int k = 0; k < DD; k++) dreg[k] *= inv;
    }
#pragma unroll
    for (int k = 0; k < DD; k++) sd16[k * SDS + tid] = __float2bfloat16(dreg[k]);

    unsigned long long d2[DD / 2];
#pragma unroll
    for (int k = 0; k < DD / 2; k++) d2[k] = pk2(dreg[2 * k], dreg[2 * k + 1]);
    __syncthreads();

    int warp = tid >> 5, lane = tid & 31;
    float colsum = 0.f, bce = 0.f;
    const unsigned long long* s_s2 = (const unsigned long long*)s_s;
    const unsigned long long* s_c2 = (const unsigned long long*)s_c;

    for (int it = 0; it < BB; it++) {
        int b = (it + (warp << 4)) & (BB - 1);   // distinct b per warp (skew < 16)
        unsigned ow = s_bit[b * 8 + warp];            // this warp's word, row b
        unsigned sw = s_bit[s_sim[b] * 8 + warp];     // sim row (resident!)

        // interleaved dots: t = s_set[b].d ; z = common[b].d
        unsigned long long a0 = 0ull, a1 = 0ull, c0 = 0ull, c1 = 0ull;
#pragma unroll
        for (int k = 0; k < DD / 2; k += 2) {
            unsigned long long dk = d2[k], dk1 = d2[k + 1];
            ffma2(a0, dk,  s_s2[b * (DD / 2) + k]);
            ffma2(c0, dk,  s_c2[b * (DD / 2) + k]);
            ffma2(a1, dk1, s_s2[b * (DD / 2) + k + 1]);
            ffma2(c1, dk1, s_c2[b * (DD / 2) + k + 1]);
        }
        float t = hsum2(a0, a1);
        float z = hsum2(c0, c1);

        float e = __expf(-t);
        float prob = __fdividef(1.f, 1.f + e);
        float score = (t > 0.f) ? prob : 0.f;
        if (valid) out[(size_t)b * ND + n] = score;
        colsum += score;

        // BCE: relu(z) - z*cd + log(1+exp(-|z|))
        float cd = (float)((ow & sw) >> lane & 1u);
        float az = fabsf(z);
        float soft = __logf(1.f + __expf(-az));
        float term = fmaxf(z, 0.f) - z * cd + soft;
        bce += valid ? term : 0.f;

        // diff branch: xor word IS the warp ballot (binary drugs)
        unsigned m = ow ^ sw;
        if (m) {
            if (lane == 0) s_sd[b] += (float)__popc(m);
            float* accb = s_acc + b * DD + lane;
            const __nv_bfloat16* col = sd16 + lane * SDS + (warp << 5);
            unsigned mm = m;
            do {
                int j = __ffs(mm) - 1; mm &= (mm - 1);
                *accb += __bfloat162float(col[j]);
            } while (mm);
        }
        if ((it & 7) == 7) __syncthreads();   // bound skew below stagger gap
    }

    if (valid) g_colsum[n] = colsum;

    s_red[tid] = bce;
    __syncthreads();
    for (int st = 128; st; st >>= 1) {
        if (tid < st) s_red[tid] += s_red[tid + st];
        __syncthreads();
    }
    if (tid == 0) atomicAdd(&g_bce, (double)s_red[0]);
    __syncthreads();

    for (int i = tid; i < BB * DD; i += 256) atomicAdd(&g_diffacc[i], s_acc[i]);
    if (tid < BB) atomicAdd(&g_sdiff[tid], s_sd[tid]);
}

// ---------------- kernel 4: row_a segment_sum ----------------
__global__ void k_hist(const int* __restrict__ idx, const float* __restrict__ val) {
    int i = blockIdx.x * blockDim.x + threadIdx.x;
    int stride = gridDim.x * blockDim.x;
    for (int j = i; j < NNZT; j += stride)
        atomicAdd(&g_row_a[idx[j]], val[j]);
}

// ---------------- kernel 5: neg1 = dot(colsum, row_a) ----------------
__global__ void k_tail() {
    __shared__ float sred[256];
    int tid = threadIdx.x;
    int i = blockIdx.x * blockDim.x + tid;
    int stride = gridDim.x * blockDim.x;
    float acc = 0.f;
    for (int j = i; j < ND; j += stride) acc += g_colsum[j] * g_row_a[j];
    sred[tid] = acc;
    __syncthreads();
    for (int st = 128; st; st >>= 1) {
        if (tid < st) sred[tid] += sred[tid + st];
        __syncthreads();
    }
    if (tid == 0) atomicAdd(&g_neg1, (double)sred[0]);
}

// ---------------- kernel 6: scalars ----------------
__global__ void k_final(float* __restrict__ out) {
    int b = threadIdx.x;   // 128 threads
    __shared__ float sred[BB];
    float acc = 0.f;
    float sdv = g_sdiff[b] + 1e-6f;
#pragma unroll
    for (int k = 0; k < DD; k++) {
        float de = g_diffacc[b * DD + k] / sdv;
        float x = g_common[b * DD + k] * de;
        acc += 1.0f / (1.0f + __expf(-x));
    }
    sred[b] = acc;
    __syncthreads();
    for (int st = 64; st; st >>= 1) {
        if (b < st) sred[b] += sred[b + st];
        __syncthreads();
    }
    if (b == 0) {
        out[(size_t)BB * ND]     = (float)(g_bce / (double)((double)BB * (double)ND));
        out[(size_t)BB * ND + 1] = (float)(1e-6 * g_neg1 + 1e-4 * (double)sred[0]);
    }
}

// ---------------- launcher ----------------
extern "C" void kernel_launch(void* const* d_in, const int* in_sizes, int n_in,
                              void* d_out, int out_size) {
    const int*   syms     = (const int*)d_in[0];
    const float* drugs    = (const float*)d_in[1];
    const int*   simidx   = (const int*)d_in[2];
    const int*   ddi_idx  = (const int*)d_in[3];
    const float* ddi_val  = (const float*)d_in[4];
    const float* sym_emb  = (const float*)d_in[5];
    const float* drug_emb = (const float*)d_in[6];
    const float* attn_w   = (const float*)d_in[7];
    const float* attn_b   = (const float*)d_in[8];
    float* out = (float*)d_out;

    static bool attr_set = false;
    const int smem_bytes = (DD * SDS) * 2 + (3 * BB * DD) * 4 + BB * 8 * 4
                         + BB * 4 + 256 * 4 + BB * 4;
    if (!attr_set) {
        cudaFuncSetAttribute(k_main, cudaFuncAttributeMaxDynamicSharedMemorySize, smem_bytes);
        attr_set = true;
    }

    k_init<<<512, 256>>>();
    k_pack<<<1024, 256>>>(drugs);
    k_attn<<<BB, SS>>>(syms, simidx, sym_emb, attn_w, attn_b);
    int nb = (ND + TN - 1) / TN;
    k_main<<<nb, 256, smem_bytes>>>(simidx, drug_emb, out);   // captured slot #4
    k_hist<<<2048, 256>>>(ddi_idx, ddi_val);
    k_tail<<<256, 256>>>();
    k_final<<<1, BB>>>(out);
}

// round 4
// speedup vs baseline: 1.1999x; 1.1999x over previous
#include <cuda_runtime.h>
#include <cuda_bf16.h>
#include <cstdint>

#define BB   128
#define SS   64
#define DD   32
#define ND   200000
#define NNZT 4000000
#define TN   256
#define SDS  258   // bf16 sd stride: 129 f32-banks -> conflict-free column reads

// ---------------- device scratch ----------------
__device__ float  g_s_set[BB * DD];
__device__ float  g_common[BB * DD];
__device__ float  g_row_a[ND];
__device__ float  g_diffacc[BB * DD];
__device__ float  g_sdiff[BB];
__device__ double g_bce;
__device__ double g_neg1;

// ---------------- packed f32x2 helpers ----------------
__device__ __forceinline__ unsigned long long pk2(float lo, float hi) {
    unsigned long long r;
    asm("mov.b64 %0, {%1, %2};" : "=l"(r) : "f"(lo), "f"(hi));
    return r;
}
__device__ __forceinline__ void ffma2(unsigned long long& acc,
                                      unsigned long long a, unsigned long long b) {
    asm("fma.rn.f32x2 %0, %1, %2, %0;" : "+l"(acc) : "l"(a), "l"(b));
}
__device__ __forceinline__ float hsum2(unsigned long long a, unsigned long long b) {
    unsigned long long s;
    asm("add.rn.f32x2 %0, %1, %2;" : "=l"(s) : "l"(a), "l"(b));
    float x, y;
    asm("mov.b64 {%0, %1}, %2;" : "=f"(x), "=f"(y) : "l"(s));
    return x + y;
}
__device__ __forceinline__ float fast_tanh(float x) {
    float r;
    asm("tanh.approx.f32 %0, %1;" : "=f"(r) : "f"(x));
    return r;
}

// ---------------- kernel 0: zero accumulators ----------------
__global__ void k_init() {
    int i = blockIdx.x * blockDim.x + threadIdx.x;
    int stride = gridDim.x * blockDim.x;
    for (int j = i; j < ND; j += stride) g_row_a[j] = 0.f;
    if (i < BB * DD) g_diffacc[i] = 0.f;
    if (i < BB) g_sdiff[i] = 0.f;
    if (i == 0) { g_bce = 0.0; g_neg1 = 0.0; }
}

// ---------------- kernel 1: row_a segment_sum ----------------
__global__ void k_hist(const int* __restrict__ idx, const float* __restrict__ val) {
    int i = blockIdx.x * blockDim.x + threadIdx.x;
    int stride = gridDim.x * blockDim.x;
    for (int j = i; j < NNZT; j += stride)
        atomicAdd(&g_row_a[idx[j]], val[j]);
}

// ---------------- kernel 2: s_set (normalized) + common_embed ----------------
__global__ void k_attn(const int* __restrict__ syms, const int* __restrict__ simidx,
                       const float* __restrict__ sym_emb,
                       const float* __restrict__ w, const float* __restrict__ bvec) {
    int b = blockIdx.x;
    int s = threadIdx.x;
    __shared__ float sw[DD];
    __shared__ float sl[SS];
    __shared__ float sred[SS][DD];
    __shared__ float smax, ssum;
    if (s < DD) sw[s] = w[s];
    float b0 = bvec[0];
    __syncthreads();

    // ---- phase A: s_set ----
    int sym = syms[b * SS + s];
    float x[DD];
    {
        const float4* rp = (const float4*)(sym_emb + (size_t)sym * DD);
#pragma unroll
        for (int q = 0; q < DD / 4; q++) {
            float4 v = rp[q];
            x[4 * q + 0] = v.x; x[4 * q + 1] = v.y; x[4 * q + 2] = v.z; x[4 * q + 3] = v.w;
        }
    }
    float lg = 0.f;
#pragma unroll
    for (int k = 0; k < DD; k++) lg += x[k] * sw[k];
    lg += b0;
    sl[s] = lg;
    __syncthreads();
    if (s == 0) { float m = sl[0]; for (int j = 1; j < SS; j++) m = fmaxf(m, sl[j]); smax = m; }
    __syncthreads();
    float e = expf(lg - smax);
    sl[s] = e;
    __syncthreads();
    if (s == 0) { float t = 0.f; for (int j = 0; j < SS; j++) t += sl[j]; ssum = t; }
    __syncthreads();
    float alpha = e / ssum;
#pragma unroll
    for (int k = 0; k < DD; k++) sred[s][k] = alpha * x[k];
    __syncthreads();
    if (s < DD) {
        float acc = 0.f;
        for (int j = 0; j < SS; j++) acc += sred[j][s];
        float sq = acc * acc;
#pragma unroll
        for (int off = 16; off; off >>= 1) sq += __shfl_xor_sync(0xffffffffu, sq, off);
        float nrm = fmaxf(sqrtf(sq), 1e-12f);
        g_s_set[b * DD + s] = acc / nrm;
    }
    __syncthreads();

    // ---- phase B: common_embed ----
    int sb = simidx[b];
    int sym2 = syms[sb * SS + s];
    float vals = (float)(sym * sym2);
    float y[DD];
    {
        const float4* rp = (const float4*)(sym_emb + (size_t)s * DD);
#pragma unroll
        for (int q = 0; q < DD / 4; q++) {
            float4 v = rp[q];
            y[4 * q + 0] = vals * v.x; y[4 * q + 1] = vals * v.y;
            y[4 * q + 2] = vals * v.z; y[4 * q + 3] = vals * v.w;
        }
    }
    lg = 0.f;
#pragma unroll
    for (int k = 0; k < DD; k++) lg += y[k] * sw[k];
    lg += b0;
    sl[s] = lg;
    __syncthreads();
    if (s == 0) { float m = sl[0]; for (int j = 1; j < SS; j++) m = fmaxf(m, sl[j]); smax = m; }
    __syncthreads();
    e = expf(lg - smax);
    sl[s] = e;
    __syncthreads();
    if (s == 0) { float t = 0.f; for (int j = 0; j < SS; j++) t += sl[j]; ssum = t; }
    __syncthreads();
    alpha = e / ssum;
#pragma unroll
    for (int k = 0; k < DD; k++) sred[s][k] = alpha * y[k];
    __syncthreads();
    if (s < DD) {
        float acc = 0.f;
        for (int j = 0; j < SS; j++) acc += sred[j][s];
        g_common[b * DD + s] = acc;
    }
}

// ---------------- kernel 3: fused mainloop ----------------
__global__ void __launch_bounds__(256, 3) k_main(
    const float* __restrict__ drugs, const int* __restrict__ simidx,
    const float* __restrict__ drug_emb, float* __restrict__ out) {
    extern __shared__ float smem[];
    __nv_bfloat16* sd16 = (__nv_bfloat16*)smem;         // [DD][SDS] bf16
    float* s_s   = smem + (DD * SDS) / 2;               // [BB*DD]
    float* s_c   = s_s + BB * DD;                       // [BB*DD]
    float* s_acc = s_c + BB * DD;                       // [BB*DD]
    float* s_sd  = s_acc + BB * DD;                     // [BB]
    float* s_red = s_sd + BB;                           // [256]
    int*   s_sim = (int*)(s_red + 256);                 // [BB]

    int tid = threadIdx.x;
    int n0 = blockIdx.x * TN;
    int n = n0 + tid;
    bool valid = (n < ND);

    for (int i = tid; i < BB * DD; i += 256) {
        s_s[i] = g_s_set[i];
        s_c[i] = g_common[i];
        s_acc[i] = 0.f;
    }
    if (tid < BB) { s_sim[tid] = simidx[tid]; s_sd[tid] = 0.f; }

    // per-thread d row, normalize in regs
    float dreg[DD];
    {
        int gn = valid ? n : (ND - 1);
        const float4* rp = (const float4*)(drug_emb + (size_t)(gn + 1) * DD);
        float sqs = 0.f;
#pragma unroll
        for (int q = 0; q < DD / 4; q++) {
            float4 v = rp[q];
            dreg[4 * q + 0] = v.x; dreg[4 * q + 1] = v.y;
            dreg[4 * q + 2] = v.z; dreg[4 * q + 3] = v.w;
            sqs += v.x * v.x + v.y * v.y + v.z * v.z + v.w * v.w;
        }
        float inv = 1.0f / fmaxf(sqrtf(sqs), 1e-12f);
        if (!valid) inv = 0.f;
#pragma unroll
        for (int k = 0; k < DD; k++) dreg[k] *= inv;
    }
#pragma unroll
    for (int k = 0; k < DD; k++) sd16[k * SDS + tid] = __float2bfloat16(dreg[k]);

    unsigned long long d2[DD / 2];
#pragma unroll
    for (int k = 0; k < DD / 2; k++) d2[k] = pk2(dreg[2 * k], dreg[2 * k + 1]);
    __syncthreads();

    int warp = tid >> 5, lane = tid & 31;
    float colsum = 0.f, bce = 0.f;
    const ulonglong2* s_s4 = (const ulonglong2*)s_s;    // 16B vectors of s_set
    const ulonglong2* s_c4 = (const ulonglong2*)s_c;

    // software-pipelined drugs loads (latency proven hidden; keep depth 1)
    int b_cur = (warp << 4) & (BB - 1);
    float db = valid ? drugs[(size_t)b_cur * ND + n] : 0.f;
    float ds = valid ? drugs[(size_t)s_sim[b_cur] * ND + n] : 0.f;

    for (int it = 0; it < BB; it++) {
        int b = b_cur;
        int b_nxt = (it + 1 + (warp << 4)) & (BB - 1);
        float db_n = 0.f, ds_n = 0.f;
        if (it + 1 < BB && valid) {
            db_n = drugs[(size_t)b_nxt * ND + n];
            ds_n = drugs[(size_t)s_sim[b_nxt] * ND + n];
        }

        // dual dot via LDS.128: t = s_set[b].d ; z = common[b].d
        unsigned long long a0 = 0ull, a1 = 0ull, c0 = 0ull, c1 = 0ull;
#pragma unroll
        for (int k = 0; k < DD / 4; k++) {
            ulonglong2 sv = s_s4[b * (DD / 4) + k];
            ulonglong2 cv = s_c4[b * (DD / 4) + k];
            unsigned long long dk = d2[2 * k], dk1 = d2[2 * k + 1];
            ffma2(a0, dk,  sv.x);
            ffma2(c0, dk,  cv.x);
            ffma2(a1, dk1, sv.y);
            ffma2(c1, dk1, cv.y);
        }
        float t = hsum2(a0, a1);
        float z = hsum2(c0, c1);

        // sigmoid via HW tanh: sig(t) = 0.5*tanh(t/2)+0.5
        float th = fast_tanh(0.5f * t);
        float score = (t > 0.f) ? __fmaf_rn(0.5f, th, 0.5f) : 0.f;
        if (valid) out[(size_t)b * ND + n] = score;
        colsum += score;

        // BCE: relu(z) - z*cd + log(1+exp(-|z|))
        float cd = db * ds;
        float az = fabsf(z);
        float soft = __logf(1.f + __expf(-az));
        float term = fmaxf(z, 0.f) - z * cd + soft;
        bce += valid ? term : 0.f;

        // diff branch: ballot-compacted bf16 adds (warp owns b via stagger)
        unsigned m = __ballot_sync(0xffffffffu, db != ds);
        if (m) {
            if (lane == 0) s_sd[b] += (float)__popc(m);
            float* accb = s_acc + b * DD + lane;
            const __nv_bfloat16* col = sd16 + lane * SDS + (warp << 5);
            unsigned mm = m;
            do {
                int j = __ffs(mm) - 1; mm &= (mm - 1);
                *accb += __bfloat162float(col[j]);
            } while (mm);
        }

        db = db_n; ds = ds_n; b_cur = b_nxt;
        if ((it & 7) == 7) __syncthreads();   // bound warp skew below stagger gap
    }

    // epilogue reductions
    float v = valid ? colsum * g_row_a[n] : 0.f;   // fold neg1 dot here
    s_red[tid] = bce;
    __syncthreads();
    for (int st = 128; st; st >>= 1) {
        if (tid < st) s_red[tid] += s_red[tid + st];
        __syncthreads();
    }
    if (tid == 0) atomicAdd(&g_bce, (double)s_red[0]);
    __syncthreads();

    s_red[tid] = v;
    __syncthreads();
    for (int st = 128; st; st >>= 1) {
        if (tid < st) s_red[tid] += s_red[tid + st];
        __syncthreads();
    }
    if (tid == 0) atomicAdd(&g_neg1, (double)s_red[0]);
    __syncthreads();

    for (int i = tid; i < BB * DD; i += 256) atomicAdd(&g_diffacc[i], s_acc[i]);
    if (tid < BB) atomicAdd(&g_sdiff[tid], s_sd[tid]);
}

// ---------------- kernel 4: scalars ----------------
__global__ void k_final(float* __restrict__ out) {
    int b = threadIdx.x;   // 128 threads
    __shared__ float sred[BB];
    float acc = 0.f;
    float sdv = g_sdiff[b] + 1e-6f;
#pragma unroll
    for (int k = 0; k < DD; k++) {
        float de = g_diffacc[b * DD + k] / sdv;
        float x = g_common[b * DD + k] * de;
        acc += 1.0f / (1.0f + __expf(-x));
    }
    sred[b] = acc;
    __syncthreads();
    for (int st = 64; st; st >>= 1) {
        if (b < st) sred[b] += sred[b + st];
        __syncthreads();
    }
    if (b == 0) {
        out[(size_t)BB * ND]     = (float)(g_bce / (double)((double)BB * (double)ND));
        out[(size_t)BB * ND + 1] = (float)(1e-6 * g_neg1 + 1e-4 * (double)sred[0]);
    }
}

// ---------------- launcher ----------------
extern "C" void kernel_launch(void* const* d_in, const int* in_sizes, int n_in,
                              void* d_out, int out_size) {
    const int*   syms     = (const int*)d_in[0];
    const float* drugs    = (const float*)d_in[1];
    const int*   simidx   = (const int*)d_in[2];
    const int*   ddi_idx  = (const int*)d_in[3];
    const float* ddi_val  = (const float*)d_in[4];
    const float* sym_emb  = (const float*)d_in[5];
    const float* drug_emb = (const float*)d_in[6];
    const float* attn_w   = (const float*)d_in[7];
    const float* attn_b   = (const float*)d_in[8];
    float* out = (float*)d_out;

    static bool attr_set = false;
    const int smem_bytes = (DD * SDS) * 2 + (3 * BB * DD + BB + 256) * 4 + BB * 4;
    if (!attr_set) {
        cudaFuncSetAttribute(k_main, cudaFuncAttributeMaxDynamicSharedMemorySize, smem_bytes);
        attr_set = true;
    }

    k_init<<<256, 256>>>();
    k_hist<<<2048, 256>>>(ddi_idx, ddi_val);   // row_a ready before k_main
    k_attn<<<BB, SS>>>(syms, simidx, sym_emb, attn_w, attn_b);
    int nb = (ND + TN - 1) / TN;
    k_main<<<nb, 256, smem_bytes>>>(drugs, simidx, drug_emb, out);
    k_final<<<1, BB>>>(out);
}